// round 6
// baseline (speedup 1.0000x reference)
#include <cuda_runtime.h>
#include <cuda_bf16.h>
#include <math.h>
#include <stdint.h>

#define Bn 4
#define Tn 4096
#define En 256
#define Hn 4
#define Dn 64

// ---------------- device scratch ----------------
__device__ float g_cos[Tn * 32];
__device__ float g_sin[Tn * 32];
__device__ __nv_bfloat16 g_Qhi[Bn * Hn * Tn * Dn];    // (b,h,t,d) rope+scale
__device__ __nv_bfloat16 g_Qlo[Bn * Hn * Tn * Dn];
__device__ __nv_bfloat16 g_Khi[Bn * Hn * Tn * Dn];
__device__ __nv_bfloat16 g_Klo[Bn * Hn * Tn * Dn];
__device__ __nv_bfloat16 g_Vhi[Bn * Hn * Tn * Dn];
__device__ __nv_bfloat16 g_Vlo[Bn * Hn * Tn * Dn];
__device__ float g_AO[Bn * Tn * En];                  // attention out (b,t,e)

// ================= helpers =================
__device__ __forceinline__ uint32_t smem_u32(const void* p) {
    uint32_t a;
    asm("{ .reg .u64 t; cvta.to.shared.u64 t, %1; cvt.u32.u64 %0, t; }" : "=r"(a) : "l"(p));
    return a;
}
__device__ __forceinline__ uint32_t packbf(float lo, float hi) {
    uint32_t r;
    asm("cvt.rn.bf16x2.f32 %0, %1, %2;" : "=r"(r) : "f"(hi), "f"(lo));
    return r;
}
__device__ __forceinline__ float bf_lo(uint32_t p) { return __uint_as_float(p << 16); }
__device__ __forceinline__ float bf_hi(uint32_t p) { return __uint_as_float(p & 0xffff0000u); }

#define LDSM4(r0, r1, r2, r3, addr) \
    asm volatile("ldmatrix.sync.aligned.m8n8.x4.shared.b16 {%0,%1,%2,%3}, [%4];" \
                 : "=r"(r0), "=r"(r1), "=r"(r2), "=r"(r3) : "r"(addr))
#define LDSM4T(r0, r1, r2, r3, addr) \
    asm volatile("ldmatrix.sync.aligned.m8n8.x4.trans.shared.b16 {%0,%1,%2,%3}, [%4];" \
                 : "=r"(r0), "=r"(r1), "=r"(r2), "=r"(r3) : "r"(addr))
#define MMA16816(C, A, b0, b1) \
    asm volatile("mma.sync.aligned.m16n8k16.row.col.f32.bf16.bf16.f32 " \
                 "{%0,%1,%2,%3}, {%4,%5,%6,%7}, {%8,%9}, {%0,%1,%2,%3};" \
                 : "+f"((C)[0]), "+f"((C)[1]), "+f"((C)[2]), "+f"((C)[3]) \
                 : "r"((A)[0]), "r"((A)[1]), "r"((A)[2]), "r"((A)[3]), "r"(b0), "r"(b1))
#define CPA16(dst, src) \
    asm volatile("cp.async.ca.shared.global [%0], [%1], 16;" :: "r"(dst), "l"(src))
#define CPCOMMIT() asm volatile("cp.async.commit_group;" ::: "memory")
#define CPWAIT0() \
    asm volatile("cp.async.commit_group;\n\tcp.async.wait_group 0;" ::: "memory")

// ---------------- RoPE cos/sin tables ----------------
__global__ void rope_table_kernel() {
    int t = blockIdx.x;
    int j = threadIdx.x;
    float base = (j < 16) ? (float)(t & 63) : (float)(t >> 6);
    int i = j & 15;
    float freq = exp2f(-(float)i * (13.287712379549449f / 16.0f));
    float ang = base * freq;
    g_cos[t * 32 + j] = cosf(ang);
    g_sin[t * 32 + j] = sinf(ang);
}

// ---------------- mma QKV projection + bias + RoPE + split -------------------
// grid (12, 128): x = sel*4 + cb; y = 128-row block. 128 threads.
#define PRS 144
#define XHI_O 0
#define XLO_O 18432
#define WHI_O 36864
#define WLO_O 46080
#define PROJ_SMEM 55296

__global__ __launch_bounds__(128, 2) void qkv_kernel(
    const float* __restrict__ q, const float* __restrict__ k, const float* __restrict__ v,
    const float* __restrict__ Wq, const float* __restrict__ bq,
    const float* __restrict__ Wk, const float* __restrict__ bk,
    const float* __restrict__ Wv, const float* __restrict__ bv,
    const int* __restrict__ p_excl)
{
    extern __shared__ char smc[];
    uint32_t sb = smem_u32(smc);

    int sel = blockIdx.x >> 2;
    int cb  = blockIdx.x & 3;
    const float* X    = (sel == 0) ? q  : (sel == 1) ? k  : v;
    const float* W    = (sel == 0) ? Wq : (sel == 1) ? Wk : Wv;
    const float* bias = (sel == 0) ? bq : (sel == 1) ? bk : bv;

    int tid = threadIdx.x;
    int lane = tid & 31;
    int w = tid >> 5;
    int row0 = blockIdx.y * 128;

    float c[2][8][4];
    #pragma unroll
    for (int mt = 0; mt < 2; mt++)
        #pragma unroll
        for (int nb = 0; nb < 8; nb++)
            #pragma unroll
            for (int cc = 0; cc < 4; cc++) c[mt][nb][cc] = 0.0f;

    for (int k0 = 0; k0 < 256; k0 += 64) {
        // stage X tile 128x64 fp32 -> hi/lo bf16
        #pragma unroll
        for (int i = tid; i < 2048; i += 128) {
            int r = i >> 4, qd = i & 15;
            float4 f = *(const float4*)&X[(row0 + r) * 256 + k0 + qd * 4];
            uint32_t h01 = packbf(f.x, f.y);
            uint32_t h23 = packbf(f.z, f.w);
            uint32_t l01 = packbf(f.x - bf_lo(h01), f.y - bf_hi(h01));
            uint32_t l23 = packbf(f.z - bf_lo(h23), f.w - bf_hi(h23));
            *(uint2*)(smc + XHI_O + r * PRS + qd * 8) = make_uint2(h01, h23);
            *(uint2*)(smc + XLO_O + r * PRS + qd * 8) = make_uint2(l01, l23);
        }
        // stage W tile 64x64 (k-major rows)
        #pragma unroll
        for (int i = tid; i < 1024; i += 128) {
            int r = i >> 4, qd = i & 15;
            float4 f = *(const float4*)&W[(k0 + r) * 256 + cb * 64 + qd * 4];
            uint32_t h01 = packbf(f.x, f.y);
            uint32_t h23 = packbf(f.z, f.w);
            uint32_t l01 = packbf(f.x - bf_lo(h01), f.y - bf_hi(h01));
            uint32_t l23 = packbf(f.z - bf_lo(h23), f.w - bf_hi(h23));
            *(uint2*)(smc + WHI_O + r * PRS + qd * 8) = make_uint2(h01, h23);
            *(uint2*)(smc + WLO_O + r * PRS + qd * 8) = make_uint2(l01, l23);
        }
        __syncthreads();

        #pragma unroll
        for (int kp2 = 0; kp2 < 2; kp2++) {
            uint32_t ahi[2][2][4], alo[2][2][4];
            #pragma unroll
            for (int mt = 0; mt < 2; mt++) {
                uint32_t ao = (uint32_t)((w * 32 + mt * 16 + (lane & 15)) * PRS
                                         + (lane >> 4) * 16 + kp2 * 64);
                LDSM4(ahi[mt][0][0], ahi[mt][0][1], ahi[mt][0][2], ahi[mt][0][3],
                      sb + XHI_O + ao);
                LDSM4(ahi[mt][1][0], ahi[mt][1][1], ahi[mt][1][2], ahi[mt][1][3],
                      sb + XHI_O + ao + 32);
                LDSM4(alo[mt][0][0], alo[mt][0][1], alo[mt][0][2], alo[mt][0][3],
                      sb + XLO_O + ao);
                LDSM4(alo[mt][1][0], alo[mt][1][1], alo[mt][1][2], alo[mt][1][3],
                      sb + XLO_O + ao + 32);
            }
            #pragma unroll
            for (int nb = 0; nb < 8; nb++) {
                uint32_t vA = (uint32_t)(lane * PRS + kp2 * 32 * PRS + nb * 16);
                uint32_t b0, b1, b2, b3;
                LDSM4T(b0, b1, b2, b3, sb + WHI_O + vA);
                #pragma unroll
                for (int mt = 0; mt < 2; mt++) {
                    MMA16816(c[mt][nb], ahi[mt][0], b0, b1);
                    MMA16816(c[mt][nb], alo[mt][0], b0, b1);
                    MMA16816(c[mt][nb], ahi[mt][1], b2, b3);
                    MMA16816(c[mt][nb], alo[mt][1], b2, b3);
                }
                LDSM4T(b0, b1, b2, b3, sb + WLO_O + vA);
                #pragma unroll
                for (int mt = 0; mt < 2; mt++) {
                    MMA16816(c[mt][nb], ahi[mt][0], b0, b1);
                    MMA16816(c[mt][nb], ahi[mt][1], b2, b3);
                }
            }
        }
        __syncthreads();
    }

    // epilogue: bias + rope + split-bf16 store
    int nkr = Tn - *p_excl;
    __nv_bfloat16* Dhi = (sel == 0) ? g_Qhi : (sel == 1) ? g_Khi : g_Vhi;
    __nv_bfloat16* Dlo = (sel == 0) ? g_Qlo : (sel == 1) ? g_Klo : g_Vlo;
    #pragma unroll
    for (int mt = 0; mt < 2; mt++) {
        #pragma unroll
        for (int nb = 0; nb < 8; nb++) {
            int col = cb * 64 + nb * 8 + (lane & 3) * 2;
            int d = col & 63;
            float b0v = bias[col], b1v = bias[col + 1];
            #pragma unroll
            for (int hf = 0; hf < 2; hf++) {
                int row = row0 + w * 32 + mt * 16 + (lane >> 2) + hf * 8;
                int t = row & (Tn - 1);
                int b = row >> 12;
                float av = c[mt][nb][hf * 2]     + b0v;
                float bw = c[mt][nb][hf * 2 + 1] + b1v;
                float ra = av, rb = bw;
                bool doRope = (sel == 0) || (sel == 1 && t < nkr);
                if (sel < 2 && doRope) {
                    int p = d >> 1;
                    float cc = g_cos[t * 32 + p];
                    float ss = g_sin[t * 32 + p];
                    ra = av * cc - bw * ss;
                    rb = av * ss + bw * cc;
                }
                if (sel == 0) { ra *= 0.125f; rb *= 0.125f; }
                size_t idx = (((size_t)(b * Hn + cb) * Tn + t) * Dn + d);
                uint32_t hp = packbf(ra, rb);
                uint32_t lp = packbf(ra - bf_lo(hp), rb - bf_hi(hp));
                *(uint32_t*)&Dhi[idx] = hp;
                *(uint32_t*)&Dlo[idx] = lp;
            }
        }
    }
}

// ---------------- mma.sync flash attention (split-bf16, no-max softmax) ------
// grid (Tn/64, B*H), 128 threads, double-buffered K/V tiles.
#define RS 144
#define KHI_O 0
#define KLO_O 9216
#define VHI_O 18432
#define VLO_O 27648
#define BUF_SZ 36864
#define ATTN_SMEM (2 * BUF_SZ)

__global__ __launch_bounds__(128, 3) void attn_kernel() {
    extern __shared__ char smc[];
    uint32_t sb = smem_u32(smc);

    int tid  = threadIdx.x;
    int lane = tid & 31;
    int w    = tid >> 5;
    int bh = blockIdx.y;
    int t0 = blockIdx.x * 64;
    const __nv_bfloat16* Qhg = g_Qhi + (size_t)bh * Tn * Dn;
    const __nv_bfloat16* Qlg = g_Qlo + (size_t)bh * Tn * Dn;
    const __nv_bfloat16* Khg = g_Khi + (size_t)bh * Tn * Dn;
    const __nv_bfloat16* Klg = g_Klo + (size_t)bh * Tn * Dn;
    const __nv_bfloat16* Vhg = g_Vhi + (size_t)bh * Tn * Dn;
    const __nv_bfloat16* Vlg = g_Vlo + (size_t)bh * Tn * Dn;

    // ---- stage Q tile (already split) into buf0 K region ----
    #pragma unroll
    for (int i = tid; i < 512; i += 128) {
        int r = i >> 3, sg = i & 7;
        uint32_t doff = (uint32_t)(r * RS + sg * 16);
        CPA16(sb + KHI_O + doff, (const char*)(Qhg + (t0 + r) * 64) + sg * 16);
        CPA16(sb + KLO_O + doff, (const char*)(Qlg + (t0 + r) * 64) + sg * 16);
    }
    CPWAIT0();
    __syncthreads();

    uint32_t qhi[4][4], qlo[4][4];
    {
        uint32_t ao = (uint32_t)((w * 16 + (lane & 15)) * RS + (lane >> 4) * 16);
        #pragma unroll
        for (int ks = 0; ks < 4; ks++) {
            LDSM4(qhi[ks][0], qhi[ks][1], qhi[ks][2], qhi[ks][3], sb + KHI_O + ao + ks * 32);
            LDSM4(qlo[ks][0], qlo[ks][1], qlo[ks][2], qlo[ks][3], sb + KLO_O + ao + ks * 32);
        }
    }
    __syncthreads();

    float O[8][4];
    #pragma unroll
    for (int nb = 0; nb < 8; nb++)
        #pragma unroll
        for (int cc = 0; cc < 4; cc++) O[nb][cc] = 0.0f;
    float lsum0 = 0.0f, lsum1 = 0.0f;

    uint32_t kAddr = sb + (uint32_t)((lane & 7) * RS + (lane >> 3) * 16);
    uint32_t vAddr = sb + (uint32_t)(lane * RS);

    // issue tile 0 -> buf 0
    {
        int r = tid >> 1;
        uint32_t drow = (uint32_t)(r * RS) + (uint32_t)((tid & 1) * 64);
        size_t gofs = (size_t)r * 64 + (tid & 1) * 32;   // elements (64B = 32 bf16)
        #pragma unroll
        for (int j = 0; j < 4; j++) {
            CPA16(sb + KHI_O + drow + j * 16, (const char*)(Khg + gofs) + j * 16);
            CPA16(sb + KLO_O + drow + j * 16, (const char*)(Klg + gofs) + j * 16);
            CPA16(sb + VHI_O + drow + j * 16, (const char*)(Vhg + gofs) + j * 16);
            CPA16(sb + VLO_O + drow + j * 16, (const char*)(Vlg + gofs) + j * 16);
        }
        CPCOMMIT();
    }

    for (int kt = 0; kt < 64; kt++) {
        // prefetch tile kt+1 into the other buffer
        if (kt < 63) {
            uint32_t bo = (uint32_t)(((kt + 1) & 1) * BUF_SZ);
            int r = tid >> 1;
            uint32_t drow = bo + (uint32_t)(r * RS) + (uint32_t)((tid & 1) * 64);
            size_t gofs = ((size_t)(kt + 1) * 64 + r) * 64 + (tid & 1) * 32;
            #pragma unroll
            for (int j = 0; j < 4; j++) {
                CPA16(sb + KHI_O + drow + j * 16, (const char*)(Khg + gofs) + j * 16);
                CPA16(sb + KLO_O + drow + j * 16, (const char*)(Klg + gofs) + j * 16);
                CPA16(sb + VHI_O + drow + j * 16, (const char*)(Vhg + gofs) + j * 16);
                CPA16(sb + VLO_O + drow + j * 16, (const char*)(Vlg + gofs) + j * 16);
            }
            CPCOMMIT();
            asm volatile("cp.async.wait_group 1;" ::: "memory");
        } else {
            asm volatile("cp.async.wait_group 0;" ::: "memory");
        }
        __syncthreads();
        uint32_t bo = (uint32_t)((kt & 1) * BUF_SZ);

        // ---- S = Qhi*Khi + Qlo*Khi + Qhi*Klo ----
        float S[8][4];
        #pragma unroll
        for (int nb = 0; nb < 8; nb++)
            #pragma unroll
            for (int cc = 0; cc < 4; cc++) S[nb][cc] = 0.0f;

        #pragma unroll
        for (int kp = 0; kp < 2; kp++)
            #pragma unroll
            for (int nb = 0; nb < 8; nb++) {
                uint32_t b0, b1, b2, b3;
                LDSM4(b0, b1, b2, b3, kAddr + bo + KHI_O + nb * 8 * RS + kp * 64);
                MMA16816(S[nb], qhi[2 * kp],     b0, b1);
                MMA16816(S[nb], qlo[2 * kp],     b0, b1);
                MMA16816(S[nb], qhi[2 * kp + 1], b2, b3);
                MMA16816(S[nb], qlo[2 * kp + 1], b2, b3);
            }
        #pragma unroll
        for (int kp = 0; kp < 2; kp++)
            #pragma unroll
            for (int nb = 0; nb < 8; nb++) {
                uint32_t b0, b1, b2, b3;
                LDSM4(b0, b1, b2, b3, kAddr + bo + KLO_O + nb * 8 * RS + kp * 64);
                MMA16816(S[nb], qhi[2 * kp],     b0, b1);
                MMA16816(S[nb], qhi[2 * kp + 1], b2, b3);
            }

        // ---- softmax (fixed max 0) + P fragments ----
        uint32_t phi[4][4], plo[4][4];
        #pragma unroll
        for (int ks = 0; ks < 4; ks++) {
            float e0 = __expf(S[2 * ks][0]),     e1 = __expf(S[2 * ks][1]);
            float e2 = __expf(S[2 * ks][2]),     e3 = __expf(S[2 * ks][3]);
            float f0 = __expf(S[2 * ks + 1][0]), f1 = __expf(S[2 * ks + 1][1]);
            float f2 = __expf(S[2 * ks + 1][2]), f3 = __expf(S[2 * ks + 1][3]);
            lsum0 += (e0 + e1) + (f0 + f1);
            lsum1 += (e2 + e3) + (f2 + f3);
            uint32_t h;
            h = packbf(e0, e1); phi[ks][0] = h;
            plo[ks][0] = packbf(e0 - bf_lo(h), e1 - bf_hi(h));
            h = packbf(e2, e3); phi[ks][1] = h;
            plo[ks][1] = packbf(e2 - bf_lo(h), e3 - bf_hi(h));
            h = packbf(f0, f1); phi[ks][2] = h;
            plo[ks][2] = packbf(f0 - bf_lo(h), f1 - bf_hi(h));
            h = packbf(f2, f3); phi[ks][3] = h;
            plo[ks][3] = packbf(f2 - bf_lo(h), f3 - bf_hi(h));
        }

        // ---- O += Phi*Vhi + Plo*Vhi + Phi*Vlo ----
        #pragma unroll
        for (int kp = 0; kp < 2; kp++)
            #pragma unroll
            for (int nb = 0; nb < 8; nb++) {
                uint32_t b0, b1, b2, b3;
                LDSM4T(b0, b1, b2, b3, vAddr + bo + VHI_O + kp * 32 * RS + nb * 16);
                MMA16816(O[nb], phi[2 * kp],     b0, b1);
                MMA16816(O[nb], plo[2 * kp],     b0, b1);
                MMA16816(O[nb], phi[2 * kp + 1], b2, b3);
                MMA16816(O[nb], plo[2 * kp + 1], b2, b3);
            }
        #pragma unroll
        for (int kp = 0; kp < 2; kp++)
            #pragma unroll
            for (int nb = 0; nb < 8; nb++) {
                uint32_t b0, b1, b2, b3;
                LDSM4T(b0, b1, b2, b3, vAddr + bo + VLO_O + kp * 32 * RS + nb * 16);
                MMA16816(O[nb], phi[2 * kp],     b0, b1);
                MMA16816(O[nb], phi[2 * kp + 1], b2, b3);
            }
        __syncthreads();
    }

    // ---- epilogue ----
    lsum0 += __shfl_xor_sync(0xffffffffu, lsum0, 1);
    lsum0 += __shfl_xor_sync(0xffffffffu, lsum0, 2);
    lsum1 += __shfl_xor_sync(0xffffffffu, lsum1, 1);
    lsum1 += __shfl_xor_sync(0xffffffffu, lsum1, 2);
    float inv0 = 1.0f / lsum0, inv1 = 1.0f / lsum1;

    int b = bh >> 2, h = bh & 3;
    int r = lane >> 2, lam = lane & 3;
    int row0 = t0 + w * 16 + r;
    float* d0 = &g_AO[((size_t)(b * Tn + row0)) * En + h * 64 + lam * 2];
    float* d1 = &g_AO[((size_t)(b * Tn + row0 + 8)) * En + h * 64 + lam * 2];
    #pragma unroll
    for (int nb = 0; nb < 8; nb++) {
        *(float2*)(d0 + nb * 8) = make_float2(O[nb][0] * inv0, O[nb][1] * inv0);
        *(float2*)(d1 + nb * 8) = make_float2(O[nb][2] * inv1, O[nb][3] * inv1);
    }
}

// ---------------- mma output projection ----------------
// grid (4, 128), 128 threads.
__global__ __launch_bounds__(128, 2) void outproj_kernel(
    const float* __restrict__ Wo, const float* __restrict__ bo,
    float* __restrict__ out)
{
    extern __shared__ char smc[];
    uint32_t sb = smem_u32(smc);

    int cb = blockIdx.x;
    int tid = threadIdx.x;
    int lane = tid & 31;
    int w = tid >> 5;
    int row0 = blockIdx.y * 128;

    float c[2][8][4];
    #pragma unroll
    for (int mt = 0; mt < 2; mt++)
        #pragma unroll
        for (int nb = 0; nb < 8; nb++)
            #pragma unroll
            for (int cc = 0; cc < 4; cc++) c[mt][nb][cc] = 0.0f;

    for (int k0 = 0; k0 < 256; k0 += 64) {
        #pragma unroll
        for (int i = tid; i < 2048; i += 128) {
            int r = i >> 4, qd = i & 15;
            float4 f = *(const float4*)&g_AO[(size_t)(row0 + r) * 256 + k0 + qd * 4];
            uint32_t h01 = packbf(f.x, f.y);
            uint32_t h23 = packbf(f.z, f.w);
            uint32_t l01 = packbf(f.x - bf_lo(h01), f.y - bf_hi(h01));
            uint32_t l23 = packbf(f.z - bf_lo(h23), f.w - bf_hi(h23));
            *(uint2*)(smc + XHI_O + r * PRS + qd * 8) = make_uint2(h01, h23);
            *(uint2*)(smc + XLO_O + r * PRS + qd * 8) = make_uint2(l01, l23);
        }
        #pragma unroll
        for (int i = tid; i < 1024; i += 128) {
            int r = i >> 4, qd = i & 15;
            float4 f = *(const float4*)&Wo[(k0 + r) * 256 + cb * 64 + qd * 4];
            uint32_t h01 = packbf(f.x, f.y);
            uint32_t h23 = packbf(f.z, f.w);
            uint32_t l01 = packbf(f.x - bf_lo(h01), f.y - bf_hi(h01));
            uint32_t l23 = packbf(f.z - bf_lo(h23), f.w - bf_hi(h23));
            *(uint2*)(smc + WHI_O + r * PRS + qd * 8) = make_uint2(h01, h23);
            *(uint2*)(smc + WLO_O + r * PRS + qd * 8) = make_uint2(l01, l23);
        }
        __syncthreads();

        #pragma unroll
        for (int kp2 = 0; kp2 < 2; kp2++) {
            uint32_t ahi[2][2][4], alo[2][2][4];
            #pragma unroll
            for (int mt = 0; mt < 2; mt++) {
                uint32_t ao = (uint32_t)((w * 32 + mt * 16 + (lane & 15)) * PRS
                                         + (lane >> 4) * 16 + kp2 * 64);
                LDSM4(ahi[mt][0][0], ahi[mt][0][1], ahi[mt][0][2], ahi[mt][0][3],
                      sb + XHI_O + ao);
                LDSM4(ahi[mt][1][0], ahi[mt][1][1], ahi[mt][1][2], ahi[mt][1][3],
                      sb + XHI_O + ao + 32);
                LDSM4(alo[mt][0][0], alo[mt][0][1], alo[mt][0][2], alo[mt][0][3],
                      sb + XLO_O + ao);
                LDSM4(alo[mt][1][0], alo[mt][1][1], alo[mt][1][2], alo[mt][1][3],
                      sb + XLO_O + ao + 32);
            }
            #pragma unroll
            for (int nb = 0; nb < 8; nb++) {
                uint32_t vA = (uint32_t)(lane * PRS + kp2 * 32 * PRS + nb * 16);
                uint32_t b0, b1, b2, b3;
                LDSM4T(b0, b1, b2, b3, sb + WHI_O + vA);
                #pragma unroll
                for (int mt = 0; mt < 2; mt++) {
                    MMA16816(c[mt][nb], ahi[mt][0], b0, b1);
                    MMA16816(c[mt][nb], alo[mt][0], b0, b1);
                    MMA16816(c[mt][nb], ahi[mt][1], b2, b3);
                    MMA16816(c[mt][nb], alo[mt][1], b2, b3);
                }
                LDSM4T(b0, b1, b2, b3, sb + WLO_O + vA);
                #pragma unroll
                for (int mt = 0; mt < 2; mt++) {
                    MMA16816(c[mt][nb], ahi[mt][0], b0, b1);
                    MMA16816(c[mt][nb], ahi[mt][1], b2, b3);
                }
            }
        }
        __syncthreads();
    }

    #pragma unroll
    for (int mt = 0; mt < 2; mt++) {
        #pragma unroll
        for (int nb = 0; nb < 8; nb++) {
            int col = cb * 64 + nb * 8 + (lane & 3) * 2;
            float b0v = bo[col], b1v = bo[col + 1];
            #pragma unroll
            for (int hf = 0; hf < 2; hf++) {
                int row = row0 + w * 32 + mt * 16 + (lane >> 2) + hf * 8;
                *(float2*)&out[(size_t)row * 256 + col] =
                    make_float2(c[mt][nb][hf * 2] + b0v, c[mt][nb][hf * 2 + 1] + b1v);
            }
        }
    }
}

// ---------------- launcher ----------------
extern "C" void kernel_launch(void* const* d_in, const int* in_sizes, int n_in,
                              void* d_out, int out_size)
{
    (void)in_sizes; (void)n_in; (void)out_size;
    const float* q  = (const float*)d_in[0];
    const float* k  = (const float*)d_in[1];
    const float* v  = (const float*)d_in[2];
    const float* Wq = (const float*)d_in[3];
    const float* bq = (const float*)d_in[4];
    const float* Wk = (const float*)d_in[5];
    const float* bk = (const float*)d_in[6];
    const float* Wv = (const float*)d_in[7];
    const float* bv = (const float*)d_in[8];
    const float* Wo = (const float*)d_in[9];
    const float* bo = (const float*)d_in[10];
    const int* excl = (const int*)d_in[11];
    float* out = (float*)d_out;

    cudaFuncSetAttribute(qkv_kernel,
                         cudaFuncAttributeMaxDynamicSharedMemorySize, PROJ_SMEM);
    cudaFuncSetAttribute(outproj_kernel,
                         cudaFuncAttributeMaxDynamicSharedMemorySize, PROJ_SMEM);
    cudaFuncSetAttribute(attn_kernel,
                         cudaFuncAttributeMaxDynamicSharedMemorySize, ATTN_SMEM);

    rope_table_kernel<<<Tn, 32>>>();
    qkv_kernel<<<dim3(12, 128), 128, PROJ_SMEM>>>(q, k, v, Wq, bq, Wk, bk, Wv, bv, excl);
    attn_kernel<<<dim3(Tn / 64, Bn * Hn), 128, ATTN_SMEM>>>();
    outproj_kernel<<<dim3(4, 128), 128, PROJ_SMEM>>>(Wo, bo, out);
}

// round 9
// speedup vs baseline: 1.2167x; 1.2167x over previous
#include <cuda_runtime.h>
#include <cuda_bf16.h>
#include <math.h>
#include <stdint.h>

#define Bn 4
#define Tn 4096
#define En 256
#define Hn 4
#define Dn 64

// ---------------- device scratch ----------------
__device__ float g_cos[Tn * 32];
__device__ float g_sin[Tn * 32];
__device__ __nv_bfloat16 g_Qhi[Bn * Hn * Tn * Dn];    // (b,h,t,d) rope+scale
__device__ __nv_bfloat16 g_Qlo[Bn * Hn * Tn * Dn];
__device__ __nv_bfloat16 g_Khi[Bn * Hn * Tn * Dn];
__device__ __nv_bfloat16 g_Klo[Bn * Hn * Tn * Dn];
__device__ __nv_bfloat16 g_Vhi[Bn * Hn * Tn * Dn];
__device__ __nv_bfloat16 g_Vlo[Bn * Hn * Tn * Dn];
__device__ float g_AO[Bn * Tn * En];                  // attention out (b,t,e)

// ================= helpers =================
__device__ __forceinline__ uint32_t smem_u32(const void* p) {
    uint32_t a;
    asm("{ .reg .u64 t; cvta.to.shared.u64 t, %1; cvt.u32.u64 %0, t; }" : "=r"(a) : "l"(p));
    return a;
}
__device__ __forceinline__ uint32_t packbf(float lo, float hi) {
    uint32_t r;
    asm("cvt.rn.bf16x2.f32 %0, %1, %2;" : "=r"(r) : "f"(hi), "f"(lo));
    return r;
}
__device__ __forceinline__ float bf_lo(uint32_t p) { return __uint_as_float(p << 16); }
__device__ __forceinline__ float bf_hi(uint32_t p) { return __uint_as_float(p & 0xffff0000u); }

#define LDSM4(r0, r1, r2, r3, addr) \
    asm volatile("ldmatrix.sync.aligned.m8n8.x4.shared.b16 {%0,%1,%2,%3}, [%4];" \
                 : "=r"(r0), "=r"(r1), "=r"(r2), "=r"(r3) : "r"(addr))
#define LDSM4T(r0, r1, r2, r3, addr) \
    asm volatile("ldmatrix.sync.aligned.m8n8.x4.trans.shared.b16 {%0,%1,%2,%3}, [%4];" \
                 : "=r"(r0), "=r"(r1), "=r"(r2), "=r"(r3) : "r"(addr))
#define MMA16816(C, A, b0, b1) \
    asm volatile("mma.sync.aligned.m16n8k16.row.col.f32.bf16.bf16.f32 " \
                 "{%0,%1,%2,%3}, {%4,%5,%6,%7}, {%8,%9}, {%0,%1,%2,%3};" \
                 : "+f"((C)[0]), "+f"((C)[1]), "+f"((C)[2]), "+f"((C)[3]) \
                 : "r"((A)[0]), "r"((A)[1]), "r"((A)[2]), "r"((A)[3]), "r"(b0), "r"(b1))
#define CPA16(dst, src) \
    asm volatile("cp.async.ca.shared.global [%0], [%1], 16;" :: "r"(dst), "l"(src))
#define CPWAIT0() \
    asm volatile("cp.async.commit_group;\n\tcp.async.wait_group 0;" ::: "memory")

// ---------------- RoPE cos/sin tables ----------------
__global__ void rope_table_kernel() {
    int t = blockIdx.x;
    int j = threadIdx.x;
    float base = (j < 16) ? (float)(t & 63) : (float)(t >> 6);
    int i = j & 15;
    float freq = exp2f(-(float)i * (13.287712379549449f / 16.0f));
    float ang = base * freq;
    g_cos[t * 32 + j] = cosf(ang);
    g_sin[t * 32 + j] = sinf(ang);
}

// ---------------- mma QKV projection + bias + RoPE + split -------------------
// grid (12, 128): x = sel*4 + cb; y = 128-row block. 128 threads.
#define PRS 144
#define XHI_O 0
#define XLO_O 18432
#define WHI_O 36864
#define WLO_O 46080
#define PROJ_SMEM 55296

__global__ __launch_bounds__(128, 2) void qkv_kernel(
    const float* __restrict__ q, const float* __restrict__ k, const float* __restrict__ v,
    const float* __restrict__ Wq, const float* __restrict__ bq,
    const float* __restrict__ Wk, const float* __restrict__ bk,
    const float* __restrict__ Wv, const float* __restrict__ bv,
    const int* __restrict__ p_excl)
{
    extern __shared__ char smc[];
    uint32_t sb = smem_u32(smc);

    int sel = blockIdx.x >> 2;
    int cb  = blockIdx.x & 3;
    const float* X    = (sel == 0) ? q  : (sel == 1) ? k  : v;
    const float* W    = (sel == 0) ? Wq : (sel == 1) ? Wk : Wv;
    const float* bias = (sel == 0) ? bq : (sel == 1) ? bk : bv;

    int tid = threadIdx.x;
    int lane = tid & 31;
    int w = tid >> 5;
    int row0 = blockIdx.y * 128;

    float c[2][8][4];
    #pragma unroll
    for (int mt = 0; mt < 2; mt++)
        #pragma unroll
        for (int nb = 0; nb < 8; nb++)
            #pragma unroll
            for (int cc = 0; cc < 4; cc++) c[mt][nb][cc] = 0.0f;

    for (int k0 = 0; k0 < 256; k0 += 64) {
        // stage X tile 128x64 fp32 -> hi/lo bf16
        #pragma unroll
        for (int i = tid; i < 2048; i += 128) {
            int r = i >> 4, qd = i & 15;
            float4 f = *(const float4*)&X[(row0 + r) * 256 + k0 + qd * 4];
            uint32_t h01 = packbf(f.x, f.y);
            uint32_t h23 = packbf(f.z, f.w);
            uint32_t l01 = packbf(f.x - bf_lo(h01), f.y - bf_hi(h01));
            uint32_t l23 = packbf(f.z - bf_lo(h23), f.w - bf_hi(h23));
            *(uint2*)(smc + XHI_O + r * PRS + qd * 8) = make_uint2(h01, h23);
            *(uint2*)(smc + XLO_O + r * PRS + qd * 8) = make_uint2(l01, l23);
        }
        // stage W tile 64x64 (k-major rows)
        #pragma unroll
        for (int i = tid; i < 1024; i += 128) {
            int r = i >> 4, qd = i & 15;
            float4 f = *(const float4*)&W[(k0 + r) * 256 + cb * 64 + qd * 4];
            uint32_t h01 = packbf(f.x, f.y);
            uint32_t h23 = packbf(f.z, f.w);
            uint32_t l01 = packbf(f.x - bf_lo(h01), f.y - bf_hi(h01));
            uint32_t l23 = packbf(f.z - bf_lo(h23), f.w - bf_hi(h23));
            *(uint2*)(smc + WHI_O + r * PRS + qd * 8) = make_uint2(h01, h23);
            *(uint2*)(smc + WLO_O + r * PRS + qd * 8) = make_uint2(l01, l23);
        }
        __syncthreads();

        #pragma unroll
        for (int kp2 = 0; kp2 < 2; kp2++) {
            uint32_t ahi[2][2][4], alo[2][2][4];
            #pragma unroll
            for (int mt = 0; mt < 2; mt++) {
                uint32_t ao = (uint32_t)((w * 32 + mt * 16 + (lane & 15)) * PRS
                                         + (lane >> 4) * 16 + kp2 * 64);
                LDSM4(ahi[mt][0][0], ahi[mt][0][1], ahi[mt][0][2], ahi[mt][0][3],
                      sb + XHI_O + ao);
                LDSM4(ahi[mt][1][0], ahi[mt][1][1], ahi[mt][1][2], ahi[mt][1][3],
                      sb + XHI_O + ao + 32);
                LDSM4(alo[mt][0][0], alo[mt][0][1], alo[mt][0][2], alo[mt][0][3],
                      sb + XLO_O + ao);
                LDSM4(alo[mt][1][0], alo[mt][1][1], alo[mt][1][2], alo[mt][1][3],
                      sb + XLO_O + ao + 32);
            }
            #pragma unroll
            for (int nb = 0; nb < 8; nb++) {
                uint32_t vA = (uint32_t)(lane * PRS + kp2 * 32 * PRS + nb * 16);
                uint32_t b0, b1, b2, b3;
                LDSM4T(b0, b1, b2, b3, sb + WHI_O + vA);
                #pragma unroll
                for (int mt = 0; mt < 2; mt++) {
                    MMA16816(c[mt][nb], ahi[mt][0], b0, b1);
                    MMA16816(c[mt][nb], alo[mt][0], b0, b1);
                    MMA16816(c[mt][nb], ahi[mt][1], b2, b3);
                    MMA16816(c[mt][nb], alo[mt][1], b2, b3);
                }
                LDSM4T(b0, b1, b2, b3, sb + WLO_O + vA);
                #pragma unroll
                for (int mt = 0; mt < 2; mt++) {
                    MMA16816(c[mt][nb], ahi[mt][0], b0, b1);
                    MMA16816(c[mt][nb], ahi[mt][1], b2, b3);
                }
            }
        }
        __syncthreads();
    }

    // epilogue: bias + rope + split-bf16 store
    int nkr = Tn - *p_excl;
    __nv_bfloat16* Dhi = (sel == 0) ? g_Qhi : (sel == 1) ? g_Khi : g_Vhi;
    __nv_bfloat16* Dlo = (sel == 0) ? g_Qlo : (sel == 1) ? g_Klo : g_Vlo;
    #pragma unroll
    for (int mt = 0; mt < 2; mt++) {
        #pragma unroll
        for (int nb = 0; nb < 8; nb++) {
            int col = cb * 64 + nb * 8 + (lane & 3) * 2;
            int d = col & 63;
            float b0v = bias[col], b1v = bias[col + 1];
            #pragma unroll
            for (int hf = 0; hf < 2; hf++) {
                int row = row0 + w * 32 + mt * 16 + (lane >> 2) + hf * 8;
                int t = row & (Tn - 1);
                int b = row >> 12;
                float av = c[mt][nb][hf * 2]     + b0v;
                float bw = c[mt][nb][hf * 2 + 1] + b1v;
                float ra = av, rb = bw;
                bool doRope = (sel == 0) || (sel == 1 && t < nkr);
                if (sel < 2 && doRope) {
                    int p = d >> 1;
                    float cc = g_cos[t * 32 + p];
                    float ss = g_sin[t * 32 + p];
                    ra = av * cc - bw * ss;
                    rb = av * ss + bw * cc;
                }
                if (sel == 0) { ra *= 0.125f; rb *= 0.125f; }
                size_t idx = (((size_t)(b * Hn + cb) * Tn + t) * Dn + d);
                uint32_t hp = packbf(ra, rb);
                uint32_t lp = packbf(ra - bf_lo(hp), rb - bf_hi(hp));
                *(uint32_t*)&Dhi[idx] = hp;
                *(uint32_t*)&Dlo[idx] = lp;
            }
        }
    }
}

// ---------------- mma.sync flash attention (split-bf16, no-max softmax) ------
// grid (Tn/64, B*H), 128 threads. Single K/V buffer (proven R4 mainloop).
#define RS 144
#define KHI_O 0
#define KLO_O 9216
#define VHI_O 18432
#define VLO_O 27648
#define ATTN_SMEM 36864

__global__ __launch_bounds__(128, 3) void attn_kernel() {
    extern __shared__ char smc[];
    uint32_t sb = smem_u32(smc);

    int tid  = threadIdx.x;
    int lane = tid & 31;
    int w    = tid >> 5;
    int bh = blockIdx.y;
    int t0 = blockIdx.x * 64;
    const __nv_bfloat16* Qhg = g_Qhi + (size_t)bh * Tn * Dn;
    const __nv_bfloat16* Qlg = g_Qlo + (size_t)bh * Tn * Dn;

    // ---- stage Q tile (already split) into K region of the buffer ----
    #pragma unroll
    for (int i = tid; i < 512; i += 128) {
        int r = i >> 3, sg = i & 7;
        uint32_t doff = (uint32_t)(r * RS + sg * 16);
        CPA16(sb + KHI_O + doff, (const char*)(Qhg + (t0 + r) * 64) + sg * 16);
        CPA16(sb + KLO_O + doff, (const char*)(Qlg + (t0 + r) * 64) + sg * 16);
    }
    CPWAIT0();
    __syncthreads();

    uint32_t qhi[4][4], qlo[4][4];
    {
        uint32_t ao = (uint32_t)((w * 16 + (lane & 15)) * RS + (lane >> 4) * 16);
        #pragma unroll
        for (int ks = 0; ks < 4; ks++) {
            LDSM4(qhi[ks][0], qhi[ks][1], qhi[ks][2], qhi[ks][3], sb + KHI_O + ao + ks * 32);
            LDSM4(qlo[ks][0], qlo[ks][1], qlo[ks][2], qlo[ks][3], sb + KLO_O + ao + ks * 32);
        }
    }
    __syncthreads();

    float O[8][4];
    #pragma unroll
    for (int nb = 0; nb < 8; nb++)
        #pragma unroll
        for (int cc = 0; cc < 4; cc++) O[nb][cc] = 0.0f;
    float lsum0 = 0.0f, lsum1 = 0.0f;

    uint32_t kAddr = sb + (uint32_t)((lane & 7) * RS + (lane >> 3) * 16);
    uint32_t vAddr = sb + (uint32_t)(lane * RS);

    // per-thread global source pointers, advanced 8192 B per k-tile
    uint32_t drow = (uint32_t)((tid >> 1) * RS) + (uint32_t)((tid & 1) * 64);
    size_t gofs = ((size_t)bh * Tn + (tid >> 1)) * Dn + (tid & 1) * 32;
    const char* pKh = (const char*)(g_Khi + gofs);
    const char* pKl = (const char*)(g_Klo + gofs);
    const char* pVh = (const char*)(g_Vhi + gofs);
    const char* pVl = (const char*)(g_Vlo + gofs);

    for (int kt = 0; kt < 64; kt++) {
        // ---- load K/V hi/lo tiles via cp.async ----
        #pragma unroll
        for (int j = 0; j < 4; j++) {
            CPA16(sb + KHI_O + drow + j * 16, pKh + j * 16);
            CPA16(sb + KLO_O + drow + j * 16, pKl + j * 16);
            CPA16(sb + VHI_O + drow + j * 16, pVh + j * 16);
            CPA16(sb + VLO_O + drow + j * 16, pVl + j * 16);
        }
        CPWAIT0();
        pKh += 8192; pKl += 8192; pVh += 8192; pVl += 8192;
        __syncthreads();

        // ---- S = Qhi*Khi + Qlo*Khi + Qhi*Klo ----
        float S[8][4];
        #pragma unroll
        for (int nb = 0; nb < 8; nb++)
            #pragma unroll
            for (int cc = 0; cc < 4; cc++) S[nb][cc] = 0.0f;

        #pragma unroll
        for (int kp = 0; kp < 2; kp++)
            #pragma unroll
            for (int nb = 0; nb < 8; nb++) {
                uint32_t b0, b1, b2, b3;
                LDSM4(b0, b1, b2, b3, kAddr + KHI_O + nb * 8 * RS + kp * 64);
                MMA16816(S[nb], qhi[2 * kp],     b0, b1);
                MMA16816(S[nb], qlo[2 * kp],     b0, b1);
                MMA16816(S[nb], qhi[2 * kp + 1], b2, b3);
                MMA16816(S[nb], qlo[2 * kp + 1], b2, b3);
            }
        #pragma unroll
        for (int kp = 0; kp < 2; kp++)
            #pragma unroll
            for (int nb = 0; nb < 8; nb++) {
                uint32_t b0, b1, b2, b3;
                LDSM4(b0, b1, b2, b3, kAddr + KLO_O + nb * 8 * RS + kp * 64);
                MMA16816(S[nb], qhi[2 * kp],     b0, b1);
                MMA16816(S[nb], qhi[2 * kp + 1], b2, b3);
            }

        // ---- softmax (fixed max 0) + P fragments ----
        uint32_t phi[4][4], plo[4][4];
        #pragma unroll
        for (int ks = 0; ks < 4; ks++) {
            float e0 = __expf(S[2 * ks][0]),     e1 = __expf(S[2 * ks][1]);
            float e2 = __expf(S[2 * ks][2]),     e3 = __expf(S[2 * ks][3]);
            float f0 = __expf(S[2 * ks + 1][0]), f1 = __expf(S[2 * ks + 1][1]);
            float f2 = __expf(S[2 * ks + 1][2]), f3 = __expf(S[2 * ks + 1][3]);
            lsum0 += (e0 + e1) + (f0 + f1);
            lsum1 += (e2 + e3) + (f2 + f3);
            uint32_t h;
            h = packbf(e0, e1); phi[ks][0] = h;
            plo[ks][0] = packbf(e0 - bf_lo(h), e1 - bf_hi(h));
            h = packbf(e2, e3); phi[ks][1] = h;
            plo[ks][1] = packbf(e2 - bf_lo(h), e3 - bf_hi(h));
            h = packbf(f0, f1); phi[ks][2] = h;
            plo[ks][2] = packbf(f0 - bf_lo(h), f1 - bf_hi(h));
            h = packbf(f2, f3); phi[ks][3] = h;
            plo[ks][3] = packbf(f2 - bf_lo(h), f3 - bf_hi(h));
        }

        // ---- O += Phi*Vhi + Plo*Vhi + Phi*Vlo ----
        #pragma unroll
        for (int kp = 0; kp < 2; kp++)
            #pragma unroll
            for (int nb = 0; nb < 8; nb++) {
                uint32_t b0, b1, b2, b3;
                LDSM4T(b0, b1, b2, b3, vAddr + VHI_O + kp * 32 * RS + nb * 16);
                MMA16816(O[nb], phi[2 * kp],     b0, b1);
                MMA16816(O[nb], plo[2 * kp],     b0, b1);
                MMA16816(O[nb], phi[2 * kp + 1], b2, b3);
                MMA16816(O[nb], plo[2 * kp + 1], b2, b3);
            }
        #pragma unroll
        for (int kp = 0; kp < 2; kp++)
            #pragma unroll
            for (int nb = 0; nb < 8; nb++) {
                uint32_t b0, b1, b2, b3;
                LDSM4T(b0, b1, b2, b3, vAddr + VLO_O + kp * 32 * RS + nb * 16);
                MMA16816(O[nb], phi[2 * kp],     b0, b1);
                MMA16816(O[nb], phi[2 * kp + 1], b2, b3);
            }
        __syncthreads();
    }

    // ---- epilogue ----
    lsum0 += __shfl_xor_sync(0xffffffffu, lsum0, 1);
    lsum0 += __shfl_xor_sync(0xffffffffu, lsum0, 2);
    lsum1 += __shfl_xor_sync(0xffffffffu, lsum1, 1);
    lsum1 += __shfl_xor_sync(0xffffffffu, lsum1, 2);
    float inv0 = 1.0f / lsum0, inv1 = 1.0f / lsum1;

    int b = bh >> 2, h = bh & 3;
    int r = lane >> 2, lam = lane & 3;
    int row0 = t0 + w * 16 + r;
    float* d0 = &g_AO[((size_t)(b * Tn + row0)) * En + h * 64 + lam * 2];
    float* d1 = &g_AO[((size_t)(b * Tn + row0 + 8)) * En + h * 64 + lam * 2];
    #pragma unroll
    for (int nb = 0; nb < 8; nb++) {
        *(float2*)(d0 + nb * 8) = make_float2(O[nb][0] * inv0, O[nb][1] * inv0);
        *(float2*)(d1 + nb * 8) = make_float2(O[nb][2] * inv1, O[nb][3] * inv1);
    }
}

// ---------------- mma output projection ----------------
// grid (4, 128), 128 threads.
__global__ __launch_bounds__(128, 2) void outproj_kernel(
    const float* __restrict__ Wo, const float* __restrict__ bo,
    float* __restrict__ out)
{
    extern __shared__ char smc[];
    uint32_t sb = smem_u32(smc);

    int cb = blockIdx.x;
    int tid = threadIdx.x;
    int lane = tid & 31;
    int w = tid >> 5;
    int row0 = blockIdx.y * 128;

    float c[2][8][4];
    #pragma unroll
    for (int mt = 0; mt < 2; mt++)
        #pragma unroll
        for (int nb = 0; nb < 8; nb++)
            #pragma unroll
            for (int cc = 0; cc < 4; cc++) c[mt][nb][cc] = 0.0f;

    for (int k0 = 0; k0 < 256; k0 += 64) {
        #pragma unroll
        for (int i = tid; i < 2048; i += 128) {
            int r = i >> 4, qd = i & 15;
            float4 f = *(const float4*)&g_AO[(size_t)(row0 + r) * 256 + k0 + qd * 4];
            uint32_t h01 = packbf(f.x, f.y);
            uint32_t h23 = packbf(f.z, f.w);
            uint32_t l01 = packbf(f.x - bf_lo(h01), f.y - bf_hi(h01));
            uint32_t l23 = packbf(f.z - bf_lo(h23), f.w - bf_hi(h23));
            *(uint2*)(smc + XHI_O + r * PRS + qd * 8) = make_uint2(h01, h23);
            *(uint2*)(smc + XLO_O + r * PRS + qd * 8) = make_uint2(l01, l23);
        }
        #pragma unroll
        for (int i = tid; i < 1024; i += 128) {
            int r = i >> 4, qd = i & 15;
            float4 f = *(const float4*)&Wo[(k0 + r) * 256 + cb * 64 + qd * 4];
            uint32_t h01 = packbf(f.x, f.y);
            uint32_t h23 = packbf(f.z, f.w);
            uint32_t l01 = packbf(f.x - bf_lo(h01), f.y - bf_hi(h01));
            uint32_t l23 = packbf(f.z - bf_lo(h23), f.w - bf_hi(h23));
            *(uint2*)(smc + WHI_O + r * PRS + qd * 8) = make_uint2(h01, h23);
            *(uint2*)(smc + WLO_O + r * PRS + qd * 8) = make_uint2(l01, l23);
        }
        __syncthreads();

        #pragma unroll
        for (int kp2 = 0; kp2 < 2; kp2++) {
            uint32_t ahi[2][2][4], alo[2][2][4];
            #pragma unroll
            for (int mt = 0; mt < 2; mt++) {
                uint32_t ao = (uint32_t)((w * 32 + mt * 16 + (lane & 15)) * PRS
                                         + (lane >> 4) * 16 + kp2 * 64);
                LDSM4(ahi[mt][0][0], ahi[mt][0][1], ahi[mt][0][2], ahi[mt][0][3],
                      sb + XHI_O + ao);
                LDSM4(ahi[mt][1][0], ahi[mt][1][1], ahi[mt][1][2], ahi[mt][1][3],
                      sb + XHI_O + ao + 32);
                LDSM4(alo[mt][0][0], alo[mt][0][1], alo[mt][0][2], alo[mt][0][3],
                      sb + XLO_O + ao);
                LDSM4(alo[mt][1][0], alo[mt][1][1], alo[mt][1][2], alo[mt][1][3],
                      sb + XLO_O + ao + 32);
            }
            #pragma unroll
            for (int nb = 0; nb < 8; nb++) {
                uint32_t vA = (uint32_t)(lane * PRS + kp2 * 32 * PRS + nb * 16);
                uint32_t b0, b1, b2, b3;
                LDSM4T(b0, b1, b2, b3, sb + WHI_O + vA);
                #pragma unroll
                for (int mt = 0; mt < 2; mt++) {
                    MMA16816(c[mt][nb], ahi[mt][0], b0, b1);
                    MMA16816(c[mt][nb], alo[mt][0], b0, b1);
                    MMA16816(c[mt][nb], ahi[mt][1], b2, b3);
                    MMA16816(c[mt][nb], alo[mt][1], b2, b3);
                }
                LDSM4T(b0, b1, b2, b3, sb + WLO_O + vA);
                #pragma unroll
                for (int mt = 0; mt < 2; mt++) {
                    MMA16816(c[mt][nb], ahi[mt][0], b0, b1);
                    MMA16816(c[mt][nb], ahi[mt][1], b2, b3);
                }
            }
        }
        __syncthreads();
    }

    #pragma unroll
    for (int mt = 0; mt < 2; mt++) {
        #pragma unroll
        for (int nb = 0; nb < 8; nb++) {
            int col = cb * 64 + nb * 8 + (lane & 3) * 2;
            float b0v = bo[col], b1v = bo[col + 1];
            #pragma unroll
            for (int hf = 0; hf < 2; hf++) {
                int row = row0 + w * 32 + mt * 16 + (lane >> 2) + hf * 8;
                *(float2*)&out[(size_t)row * 256 + col] =
                    make_float2(c[mt][nb][hf * 2] + b0v, c[mt][nb][hf * 2 + 1] + b1v);
            }
        }
    }
}

// ---------------- launcher ----------------
extern "C" void kernel_launch(void* const* d_in, const int* in_sizes, int n_in,
                              void* d_out, int out_size)
{
    (void)in_sizes; (void)n_in; (void)out_size;
    const float* q  = (const float*)d_in[0];
    const float* k  = (const float*)d_in[1];
    const float* v  = (const float*)d_in[2];
    const float* Wq = (const float*)d_in[3];
    const float* bq = (const float*)d_in[4];
    const float* Wk = (const float*)d_in[5];
    const float* bk = (const float*)d_in[6];
    const float* Wv = (const float*)d_in[7];
    const float* bv = (const float*)d_in[8];
    const float* Wo = (const float*)d_in[9];
    const float* bo = (const float*)d_in[10];
    const int* excl = (const int*)d_in[11];
    float* out = (float*)d_out;

    cudaFuncSetAttribute(qkv_kernel,
                         cudaFuncAttributeMaxDynamicSharedMemorySize, PROJ_SMEM);
    cudaFuncSetAttribute(outproj_kernel,
                         cudaFuncAttributeMaxDynamicSharedMemorySize, PROJ_SMEM);
    cudaFuncSetAttribute(attn_kernel,
                         cudaFuncAttributeMaxDynamicSharedMemorySize, ATTN_SMEM);

    rope_table_kernel<<<Tn, 32>>>();
    qkv_kernel<<<dim3(12, 128), 128, PROJ_SMEM>>>(q, k, v, Wq, bq, Wk, bk, Wv, bv, excl);
    attn_kernel<<<dim3(Tn / 64, Bn * Hn), 128, ATTN_SMEM>>>();
    outproj_kernel<<<dim3(4, 128), 128, PROJ_SMEM>>>(Wo, bo, out);
}